// round 8
// baseline (speedup 1.0000x reference)
#include <cuda_runtime.h>
#include <cuda_fp16.h>
#include <math.h>
#include <stdint.h>

#define H 96
#define W 96
#define HW (H*W)          // 9216
#define CIN 256
#define B 2
#define KK 9
#define GK (CIN*KK)       // 2304
#define GM 256
#define GN HW

// ---------------- scratch (static device allocations) -------------------------
__device__ float g_om[(size_t)B * 27 * HW];
__device__ float g_om_part[8ull * B * 27 * HW];
__device__ float g_h[(size_t)B * CIN * HW];         // layer-1 output [b][c][p]
__device__ __half g_whi[(size_t)GM * GK];           // W hi [o][r]
__device__ __half g_wlo[(size_t)GM * GK];           // W lo

// ---------------- helpers ------------------------------------------------------
__device__ __forceinline__ uint32_t sm_u32(const void* p) {
    uint32_t a;
    asm("{ .reg .u64 t; cvta.to.shared.u64 t, %1; cvt.u32.u64 %0, t; }" : "=r"(a) : "l"(p));
    return a;
}
__device__ __forceinline__ void cpasync16(uint32_t dst, const void* src) {
    asm volatile("cp.async.cg.shared.global [%0], [%1], 16;" :: "r"(dst), "l"(src));
}
#define CP_COMMIT() asm volatile("cp.async.commit_group;" ::: "memory")
#define CP_WAIT1()  asm volatile("cp.async.wait_group 1;" ::: "memory")

#define LDSM_X4(r0, r1, r2, r3, addr) \
    asm volatile("ldmatrix.sync.aligned.m8n8.x4.shared.b16 {%0,%1,%2,%3}, [%4];" \
        : "=r"(r0), "=r"(r1), "=r"(r2), "=r"(r3) : "r"(addr))
#define LDSM_X4_T(r0, r1, r2, r3, addr) \
    asm volatile("ldmatrix.sync.aligned.m8n8.x4.trans.shared.b16 {%0,%1,%2,%3}, [%4];" \
        : "=r"(r0), "=r"(r1), "=r"(r2), "=r"(r3) : "r"(addr))

#define MMA_F16(d, a, bb) \
    asm volatile("mma.sync.aligned.m16n8k16.row.col.f32.f16.f16.f32 " \
        "{%0,%1,%2,%3}, {%4,%5,%6,%7}, {%8,%9}, {%0,%1,%2,%3};" \
        : "+f"((d)[0]), "+f"((d)[1]), "+f"((d)[2]), "+f"((d)[3]) \
        : "r"((a)[0]), "r"((a)[1]), "r"((a)[2]), "r"((a)[3]), \
          "r"((bb)[0]), "r"((bb)[1]))

#define STS16(addr, v) \
    asm volatile("st.shared.u16 [%0], %1;" :: "r"(addr), "h"(v) : "memory")

// ---------------- offset conv (SMEM-tiled): grid (36,8,B), block 256 ----------
__global__ void offset_conv_kernel(const float* __restrict__ x,
                                   const float* __restrict__ w_off,
                                   float* __restrict__ om_part) {
    int b = blockIdx.z, chunk = blockIdx.y, tile = blockIdx.x;
    int h0 = (tile / 6) * 16, w0 = (tile % 6) * 16;
    int ty = threadIdx.x >> 4, tx = threadIdx.x & 15;

    float acc[27];
#pragma unroll
    for (int i = 0; i < 27; i++) acc[i] = 0.f;

    __shared__ float ws[243];
    __shared__ float xt[18 * 18];
    const float* xb = x + (size_t)b * CIN * HW;
    int c0 = chunk * 32;
    for (int c = c0; c < c0 + 32; c++) {
        __syncthreads();
        if (threadIdx.x < 243) {
            int oc = threadIdx.x / 9, k = threadIdx.x % 9;
            ws[threadIdx.x] = w_off[((size_t)oc * CIN + c) * 9 + k];
        }
        const float* xc = xb + (size_t)c * HW;
        for (int idx = threadIdx.x; idx < 324; idx += 256) {
            int yy = h0 - 1 + idx / 18, xx = w0 - 1 + idx % 18;
            xt[idx] = (yy >= 0 && yy < H && xx >= 0 && xx < W) ? xc[yy * W + xx] : 0.f;
        }
        __syncthreads();
        float xv[9];
#pragma unroll
        for (int k = 0; k < 9; k++)
            xv[k] = xt[(ty + k / 3) * 18 + tx + k % 3];
#pragma unroll
        for (int oc = 0; oc < 27; oc++)
#pragma unroll
            for (int k = 0; k < 9; k++)
                acc[oc] = fmaf(ws[oc * 9 + k], xv[k], acc[oc]);
    }
    int h = h0 + ty, w = w0 + tx;
    float* dst = om_part + ((size_t)chunk * B * 27 + (size_t)b * 27) * HW + h * W + w;
#pragma unroll
    for (int oc = 0; oc < 27; oc++) dst[(size_t)oc * HW] = acc[oc];
}

__global__ void reduce_om_kernel(const float* __restrict__ part,
                                 const float* __restrict__ b_off,
                                 float* __restrict__ om) {
    int i = blockIdx.x * 256 + threadIdx.x;
    const int N = B * 27 * HW;
    int oc = (i / HW) % 27;
    float s = b_off[oc];
#pragma unroll
    for (int j = 0; j < 8; j++) s += part[(size_t)j * N + i];
    om[i] = s;
}

// ---------------- weight split fp32 -> fp16 hi/lo -----------------------------
__global__ void wsplit_kernel(const float* __restrict__ w,
                              __half* __restrict__ whi,
                              __half* __restrict__ wlo) {
    int i = blockIdx.x * 256 + threadIdx.x;
    float v = w[i];
    __half hi = __float2half_rn(v);
    whi[i] = hi;
    wlo[i] = __float2half_rn(v - __half2float(hi));
}

// ---------------- fused deformable-im2col + fp16 split GEMM + ReLU ------------
// C[b][o][p] = relu( sum_r W[o][r] * colfused[r][p] ),
//   colfused[r][p] = mask[k][p] * bilinear(x[c], coords[k][p]),  r = c*9+k
// CTA: M=256 (all o), N=128 pixels (p0 tile), K-chunk 32, grid (72, B) = 1 wave.
#define NCH (GK / 32)                 // 72
// smem layout
#define A_STG_STRIDE 32768            // per stage: hi 16K + lo 16K
#define A_LO_OFF 16384
#define B_BASE 65536                  // per stage: hi 8K + lo 8K
#define B_STG_STRIDE 16384
#define B_LO_OFF 8192
#define TBL_BASE 98304
#define TBL_N 1152                    // 9 k x 128 p
#define SM_BYTES (TBL_BASE + 8 * TBL_N * 4)   // 135168 (132 KB)

__device__ __forceinline__ void load_stage_A(uint32_t sb, int k0, int tid,
                                             const __half* Ah, const __half* Al) {
    int row = tid;
    const __half* sh = Ah + (size_t)row * GK + k0;
    const __half* sl = Al + (size_t)row * GK + k0;
    uint32_t rbase = sb + (uint32_t)row * 64;
    uint32_t sw = (uint32_t)((row >> 1) & 3);
#pragma unroll
    for (int j = 0; j < 4; j++) {
        uint32_t d = rbase + (uint32_t)((j ^ sw) << 4);
        cpasync16(d, sh + j * 8);
        cpasync16(d + A_LO_OFF, sl + j * 8);
    }
}

__global__ __launch_bounds__(256, 1)
void gemm_fused_kernel(const __half* __restrict__ whi,
                       const __half* __restrict__ wlo,
                       const float* __restrict__ x,
                       const float* __restrict__ om,
                       float* __restrict__ out) {
    extern __shared__ char smc[];
    uint32_t smb = sm_u32(smc);
    float* tw = (float*)(smc + TBL_BASE);              // 4 arrays of TBL_N
    int*   ti = (int*)(smc + TBL_BASE + 4 * TBL_N * 4);
    const int tid = threadIdx.x;
    const int lane = tid & 31;
    const int wrp = tid >> 5;
    const int b = blockIdx.y;
    const int p0 = blockIdx.x * 128;

    const float* xb = x + (size_t)b * CIN * HW;
    const float* omb = om + (size_t)b * 27 * HW;

    // ---- build per-CTA bilinear table: (k, pl) -> 4 weights + 4 indices ----
    for (int ent = tid; ent < TBL_N; ent += 256) {
        int kk = ent >> 7, pl = ent & 127;
        int p = p0 + pl, h = p / W, w = p % W;
        float dy = omb[(size_t)(2 * kk) * HW + p];
        float dx = omb[(size_t)(2 * kk + 1) * HW + p];
        float m  = omb[(size_t)(18 + kk) * HW + p];
        m = 1.f / (1.f + __expf(-m));

        float ys = (float)(h + kk / 3 - 1) + dy;
        float xs = (float)(w + kk % 3 - 1) + dx;
        float y0f = floorf(ys), x0f = floorf(xs);
        int y0 = (int)y0f, x0 = (int)x0f;
        int y1 = y0 + 1, x1 = x0 + 1;
        float wy1 = ys - y0f, wx1 = xs - x0f;
        float wy0 = 1.f - wy1, wx0 = 1.f - wx1;

        bool vy0 = (y0 >= 0) & (y0 < H), vy1 = (y1 >= 0) & (y1 < H);
        bool vx0 = (x0 >= 0) & (x0 < W), vx1 = (x1 >= 0) & (x1 < W);
        int yc0 = min(max(y0, 0), H - 1), yc1 = min(max(y1, 0), H - 1);
        int xc0 = min(max(x0, 0), W - 1), xc1 = min(max(x1, 0), W - 1);

        tw[ent]             = wy0 * wx0 * ((vy0 & vx0) ? m : 0.f);
        tw[TBL_N + ent]     = wy0 * wx1 * ((vy0 & vx1) ? m : 0.f);
        tw[2 * TBL_N + ent] = wy1 * wx0 * ((vy1 & vx0) ? m : 0.f);
        tw[3 * TBL_N + ent] = wy1 * wx1 * ((vy1 & vx1) ? m : 0.f);
        ti[ent]             = yc0 * W + xc0;
        ti[TBL_N + ent]     = yc0 * W + xc1;
        ti[2 * TBL_N + ent] = yc1 * W + xc0;
        ti[3 * TBL_N + ent] = yc1 * W + xc1;
    }

    // ---- A prologue (cp.async, 2 stages) ----
    load_stage_A(smb, 0, tid, whi, wlo);
    CP_COMMIT();
    load_stage_A(smb + A_STG_STRIDE, 32, tid, whi, wlo);
    CP_COMMIT();
    __syncthreads();   // table visible to all; before first gather/STS

    // ---- gather for chunk 0 ----
    float vals[16];
#define GATHER(CH) do { \
        int k0g = (CH) * 32; \
        _Pragma("unroll") \
        for (int rr = 0; rr < 4; rr++) { \
            int r = k0g + wrp * 4 + rr; \
            int c = r / 9; \
            int kk = r - 9 * c; \
            const float* xc = xb + (size_t)c * HW; \
            const float* twk = tw + kk * 128; \
            const int*   tik = ti + kk * 128; \
            _Pragma("unroll") \
            for (int j = 0; j < 4; j++) { \
                int e = lane + 32 * j; \
                float v = twk[e] * __ldg(xc + tik[e]) \
                        + twk[TBL_N + e] * __ldg(xc + tik[TBL_N + e]) \
                        + twk[2 * TBL_N + e] * __ldg(xc + tik[2 * TBL_N + e]) \
                        + twk[3 * TBL_N + e] * __ldg(xc + tik[3 * TBL_N + e]); \
                vals[rr * 4 + j] = v; \
            } \
        } \
    } while (0)

    GATHER(0);

    const int wm = (wrp >> 1) * 64;
    const int wn8 = (wrp & 1) * 8;
    const int t8 = lane >> 3, r8 = lane & 7;
    const int ar = lane >> 2, ac = lane & 3;

    float acc[4][8][4];
#pragma unroll
    for (int i = 0; i < 4; i++)
#pragma unroll
        for (int j = 0; j < 8; j++)
#pragma unroll
            for (int q = 0; q < 4; q++) acc[i][j][q] = 0.f;

    for (int ch = 0; ch < NCH; ch++) {
        int st = ch & 1;
        uint32_t sbB = smb + B_BASE + (uint32_t)st * B_STG_STRIDE;

        // ---- STS: hi/lo split into ldmatrix-swizzled B buffer ----
#pragma unroll
        for (int rr = 0; rr < 4; rr++) {
            int row = wrp * 4 + rr;
            uint32_t rbase = sbB + (uint32_t)row * 256;
            uint32_t rsw = (uint32_t)(row & 7);
#pragma unroll
            for (int j = 0; j < 4; j++) {
                float v = vals[rr * 4 + j];
                __half hi = __float2half_rn(v);
                __half lo = __float2half_rn(v - __half2float(hi));
                int p = lane + 32 * j;
                uint32_t off = rbase + (uint32_t)((((uint32_t)(p >> 3)) ^ rsw) << 4)
                             + (uint32_t)(p & 7) * 2;
                STS16(off, __half_as_ushort(hi));
                STS16(off + B_LO_OFF, __half_as_ushort(lo));
            }
        }

        CP_WAIT1();
        __syncthreads();

        // ---- gather next chunk (LDG latency overlaps MMA below) ----
        if (ch + 1 < NCH) GATHER(ch + 1);

        // ---- MMA on stage st ----
        uint32_t sbA = smb + (uint32_t)st * A_STG_STRIDE;
#pragma unroll
        for (int ks = 0; ks < 2; ks++) {
            uint32_t ah[4][4], al[4][4];
#pragma unroll
            for (int mf = 0; mf < 4; mf++) {
                int mrow = wm + mf * 16 + r8 + 8 * (t8 & 1);
                int chk = 2 * ks + (t8 >> 1);
                uint32_t off = (uint32_t)mrow * 64 +
                               (uint32_t)((chk ^ ((mrow >> 1) & 3)) << 4);
                LDSM_X4(ah[mf][0], ah[mf][1], ah[mf][2], ah[mf][3], sbA + off);
                LDSM_X4(al[mf][0], al[mf][1], al[mf][2], al[mf][3], sbA + A_LO_OFF + off);
            }
#pragma unroll
            for (int np = 0; np < 4; np++) {
                uint32_t bh[4], bl[4];
                int krow = 16 * ks + r8 + 8 * (t8 & 1);
                int chkb = wn8 + np * 2 + (t8 >> 1);
                uint32_t off = (uint32_t)krow * 256 +
                               (uint32_t)((chkb ^ (krow & 7)) << 4);
                LDSM_X4_T(bh[0], bh[1], bh[2], bh[3], sbB + off);
                LDSM_X4_T(bl[0], bl[1], bl[2], bl[3], sbB + B_LO_OFF + off);
#pragma unroll
                for (int mf = 0; mf < 4; mf++)
#pragma unroll
                    for (int s = 0; s < 2; s++) {
                        float* d = acc[mf][np * 2 + s];
                        MMA_F16(d, ah[mf], &bh[s * 2]);
                        MMA_F16(d, ah[mf], &bl[s * 2]);
                        MMA_F16(d, al[mf], &bh[s * 2]);
                    }
            }
        }
        __syncthreads();

        if (ch + 2 < NCH)
            load_stage_A(smb + (uint32_t)st * A_STG_STRIDE, (ch + 2) * 32, tid,
                         whi, wlo);
        CP_COMMIT();
    }

    // ---- epilogue: ReLU + float2 stores ----
    float* Cb = out + (size_t)b * GM * GN;
    const int pb = p0 + (wrp & 1) * 64;
#pragma unroll
    for (int mf = 0; mf < 4; mf++) {
#pragma unroll
        for (int nf = 0; nf < 8; nf++) {
            int o = wm + mf * 16 + ar;
            int p = pb + nf * 8 + 2 * ac;
            float2 v0, v1;
            v0.x = fmaxf(acc[mf][nf][0], 0.f);
            v0.y = fmaxf(acc[mf][nf][1], 0.f);
            v1.x = fmaxf(acc[mf][nf][2], 0.f);
            v1.y = fmaxf(acc[mf][nf][3], 0.f);
            *(float2*)(Cb + (size_t)o * GN + p) = v0;
            *(float2*)(Cb + (size_t)(o + 8) * GN + p) = v1;
        }
    }
}

// ---------------- host side ----------------------------------------------------
static void run_layer(const float* xin, const float* w_off, const float* b_off,
                      const float* wmain, float* outp,
                      float* om, float* om_part, __half* whi, __half* wlo) {
    dim3 gOff(36, 8, B);
    offset_conv_kernel<<<gOff, 256>>>(xin, w_off, om_part);
    reduce_om_kernel<<<(B * 27 * HW) / 256, 256>>>(om_part, b_off, om);
    wsplit_kernel<<<(GM * GK) / 256, 256>>>(wmain, whi, wlo);
    dim3 gGemm(GN / 128, B);
    gemm_fused_kernel<<<gGemm, 256, SM_BYTES>>>(whi, wlo, xin, om, outp);
}

extern "C" void kernel_launch(void* const* d_in, const int* in_sizes, int n_in,
                              void* d_out, int out_size) {
    const float* x      = (const float*)d_in[0];
    const float* w_off0 = (const float*)d_in[1];
    const float* b_off0 = (const float*)d_in[2];
    const float* w0     = (const float*)d_in[3];
    const float* w_off1 = (const float*)d_in[4];
    const float* b_off1 = (const float*)d_in[5];
    const float* w1     = (const float*)d_in[6];
    float* out = (float*)d_out;

    static bool attr_set = false;
    if (!attr_set) {
        cudaFuncSetAttribute(gemm_fused_kernel,
                             cudaFuncAttributeMaxDynamicSharedMemorySize, SM_BYTES);
        attr_set = true;
    }

    __half *whi, *wlo;
    float *om, *om_part, *hbuf;
    cudaGetSymbolAddress((void**)&om,      g_om);
    cudaGetSymbolAddress((void**)&om_part, g_om_part);
    cudaGetSymbolAddress((void**)&hbuf,    g_h);
    cudaGetSymbolAddress((void**)&whi,     g_whi);
    cudaGetSymbolAddress((void**)&wlo,     g_wlo);

    run_layer(x,    w_off0, b_off0, w0, hbuf, om, om_part, whi, wlo);
    run_layer(hbuf, w_off1, b_off1, w1, out,  om, om_part, whi, wlo);
}

// round 9
// speedup vs baseline: 1.8261x; 1.8261x over previous
#include <cuda_runtime.h>
#include <cuda_bf16.h>
#include <math.h>
#include <stdint.h>

#define H 96
#define W 96
#define HW (H*W)          // 9216
#define CIN 256
#define B 2
#define KK 9
#define GK (CIN*KK)       // 2304
#define GM 256
#define GN HW

// ---------------- scratch (static device allocations) -------------------------
__device__ float g_col[(size_t)B * GK * HW];        // im2col, tf32-rounded fp32
__device__ float g_om[(size_t)B * 27 * HW];
__device__ float g_om_part[8ull * B * 27 * HW];
__device__ float g_h[(size_t)B * CIN * HW];
__device__ float g_wtf[(size_t)GM * GK];            // W, tf32-rounded fp32

// ---------------- helpers ------------------------------------------------------
__device__ __forceinline__ float to_tf32(float x) {
    float r; asm("cvt.rna.tf32.f32 %0, %1;" : "=f"(r) : "f"(x)); return r;
}
__device__ __forceinline__ uint32_t sm_u32(const void* p) {
    uint32_t a;
    asm("{ .reg .u64 t; cvta.to.shared.u64 t, %1; cvt.u32.u64 %0, t; }" : "=r"(a) : "l"(p));
    return a;
}
__device__ __forceinline__ void cpasync16(uint32_t dst, const void* src) {
    asm volatile("cp.async.cg.shared.global [%0], [%1], 16;" :: "r"(dst), "l"(src));
}
#define CP_COMMIT() asm volatile("cp.async.commit_group;" ::: "memory")
#define CP_WAIT1()  asm volatile("cp.async.wait_group 1;" ::: "memory")

#define MMA_TF32(d, a, bb) \
    asm volatile("mma.sync.aligned.m16n8k8.row.col.f32.tf32.tf32.f32 " \
        "{%0,%1,%2,%3}, {%4,%5,%6,%7}, {%8,%9}, {%0,%1,%2,%3};" \
        : "+f"((d)[0]), "+f"((d)[1]), "+f"((d)[2]), "+f"((d)[3]) \
        : "r"((a)[0]), "r"((a)[1]), "r"((a)[2]), "r"((a)[3]), \
          "r"((bb)[0]), "r"((bb)[1]))

// ---------------- offset conv (SMEM-tiled): grid (36,8,B), block 256 ----------
__global__ void offset_conv_kernel(const float* __restrict__ x,
                                   const float* __restrict__ w_off,
                                   float* __restrict__ om_part) {
    int b = blockIdx.z, chunk = blockIdx.y, tile = blockIdx.x;
    int h0 = (tile / 6) * 16, w0 = (tile % 6) * 16;
    int ty = threadIdx.x >> 4, tx = threadIdx.x & 15;

    float acc[27];
#pragma unroll
    for (int i = 0; i < 27; i++) acc[i] = 0.f;

    __shared__ float ws[243];
    __shared__ float xt[18 * 18];
    const float* xb = x + (size_t)b * CIN * HW;
    int c0 = chunk * 32;
    for (int c = c0; c < c0 + 32; c++) {
        __syncthreads();
        if (threadIdx.x < 243) {
            int oc = threadIdx.x / 9, k = threadIdx.x % 9;
            ws[threadIdx.x] = w_off[((size_t)oc * CIN + c) * 9 + k];
        }
        const float* xc = xb + (size_t)c * HW;
        for (int idx = threadIdx.x; idx < 324; idx += 256) {
            int yy = h0 - 1 + idx / 18, xx = w0 - 1 + idx % 18;
            xt[idx] = (yy >= 0 && yy < H && xx >= 0 && xx < W) ? xc[yy * W + xx] : 0.f;
        }
        __syncthreads();
        float xv[9];
#pragma unroll
        for (int k = 0; k < 9; k++)
            xv[k] = xt[(ty + k / 3) * 18 + tx + k % 3];
#pragma unroll
        for (int oc = 0; oc < 27; oc++)
#pragma unroll
            for (int k = 0; k < 9; k++)
                acc[oc] = fmaf(ws[oc * 9 + k], xv[k], acc[oc]);
    }
    int h = h0 + ty, w = w0 + tx;
    float* dst = om_part + ((size_t)chunk * B * 27 + (size_t)b * 27) * HW + h * W + w;
#pragma unroll
    for (int oc = 0; oc < 27; oc++) dst[(size_t)oc * HW] = acc[oc];
}

__global__ void reduce_om_kernel(const float* __restrict__ part,
                                 const float* __restrict__ b_off,
                                 float* __restrict__ om) {
    int i = blockIdx.x * 256 + threadIdx.x;
    const int N = B * 27 * HW;
    int oc = (i / HW) % 27;
    float s = b_off[oc];
#pragma unroll
    for (int j = 0; j < 8; j++) s += part[(size_t)j * N + i];
    om[i] = s;
}

// ---------------- deformable im2col (tf32 output, channel-split) --------------
// grid (36, 9*4, B): y encodes (cchunk, k); each block does 64 channels
__global__ void sample_kernel(const float* __restrict__ x,
                              const float* __restrict__ om,
                              float* __restrict__ col) {
    int b = blockIdx.z;
    int k = blockIdx.y % KK;
    int cc = blockIdx.y / KK;
    int p = blockIdx.x * 256 + threadIdx.x;
    int h = p / W, w = p % W;

    const float* omb = om + (size_t)b * 27 * HW;
    float dy = omb[(size_t)(2 * k) * HW + p];
    float dx = omb[(size_t)(2 * k + 1) * HW + p];
    float m  = omb[(size_t)(18 + k) * HW + p];
    m = 1.f / (1.f + __expf(-m));

    float ys = (float)(h + k / 3 - 1) + dy;
    float xs = (float)(w + k % 3 - 1) + dx;
    float y0f = floorf(ys), x0f = floorf(xs);
    int y0 = (int)y0f, x0 = (int)x0f;
    int y1 = y0 + 1, x1 = x0 + 1;
    float wy1 = ys - y0f, wx1 = xs - x0f;
    float wy0 = 1.f - wy1, wx0 = 1.f - wx1;

    bool vy0 = (y0 >= 0) & (y0 < H), vy1 = (y1 >= 0) & (y1 < H);
    bool vx0 = (x0 >= 0) & (x0 < W), vx1 = (x1 >= 0) & (x1 < W);
    int yc0 = min(max(y0, 0), H - 1), yc1 = min(max(y1, 0), H - 1);
    int xc0 = min(max(x0, 0), W - 1), xc1 = min(max(x1, 0), W - 1);

    float w00 = wy0 * wx0 * ((vy0 & vx0) ? m : 0.f);
    float w01 = wy0 * wx1 * ((vy0 & vx1) ? m : 0.f);
    float w10 = wy1 * wx0 * ((vy1 & vx0) ? m : 0.f);
    float w11 = wy1 * wx1 * ((vy1 & vx1) ? m : 0.f);

    int i00 = yc0 * W + xc0, i01 = yc0 * W + xc1;
    int i10 = yc1 * W + xc0, i11 = yc1 * W + xc1;

    const float* xb = x + (size_t)b * CIN * HW;
    float* colb = col + (size_t)b * GK * HW + (size_t)k * HW + p;
    int cbeg = cc * 64, cend = cbeg + 64;
#pragma unroll 8
    for (int c = cbeg; c < cend; c++) {
        const float* xc = xb + (size_t)c * HW;
        float v = w00 * __ldg(xc + i00) + w01 * __ldg(xc + i01)
                + w10 * __ldg(xc + i10) + w11 * __ldg(xc + i11);
        colb[(size_t)c * KK * HW] = to_tf32(v);
    }
}

// ---------------- weight tf32 pre-rounding ------------------------------------
__global__ void wcvt_kernel(const float* __restrict__ w, float* __restrict__ wt) {
    int i = blockIdx.x * 256 + threadIdx.x;
    wt[i] = to_tf32(w[i]);
}

// ---------------- tf32 mma.sync GEMM + ReLU (identical to R3) -----------------
#define NCH (GK / 32)                 // 72
#define AS_STRIDE 36
#define BS_STRIDE 132
#define AS_BUF (128 * AS_STRIDE)
#define BS_BUF (32 * BS_STRIDE)
#define SM_FLOATS (2 * AS_BUF + 2 * BS_BUF)

__global__ __launch_bounds__(256, 2)
void gemm_tf32_kernel(const float* __restrict__ A,
                      const float* __restrict__ Bm,
                      float* __restrict__ Cc) {
    extern __shared__ float sm[];
    const int tid = threadIdx.x;
    const int lane = tid & 31;
    const int wrp = tid >> 5;
    const int b = blockIdx.z;
    const int p0 = blockIdx.x * 128;
    const int m0 = blockIdx.y * 128;

    const float* Ag = A + (size_t)m0 * GK;
    const float* Bg = Bm + (size_t)b * GK * GN;

    uint32_t smb = sm_u32(sm);
    uint32_t asb[2] = { smb, smb + AS_BUF * 4 };
    uint32_t bsb[2] = { smb + 2 * AS_BUF * 4, smb + (2 * AS_BUF + BS_BUF) * 4 };

    const int am = tid >> 3, aq = tid & 7;
    const int bk = tid >> 5, bq = tid & 31;

#pragma unroll
    for (int st = 0; st < 2; st++) {
        int k0 = st * 32;
#pragma unroll
        for (int i = 0; i < 4; i++) {
            int m = am + i * 32;
            cpasync16(asb[st] + (uint32_t)(m * AS_STRIDE + aq * 4) * 4,
                      Ag + (size_t)m * GK + k0 + aq * 4);
        }
#pragma unroll
        for (int i = 0; i < 4; i++) {
            int k = bk + i * 8;
            cpasync16(bsb[st] + (uint32_t)(k * BS_STRIDE + bq * 4) * 4,
                      Bg + (size_t)(k0 + k) * GN + p0 + bq * 4);
        }
        CP_COMMIT();
    }

    const int wm = (wrp >> 2) * 64;
    const int wn = (wrp & 3) * 32;

    float acc[4][4][4];
#pragma unroll
    for (int i = 0; i < 4; i++)
#pragma unroll
        for (int j = 0; j < 4; j++)
#pragma unroll
            for (int q = 0; q < 4; q++) acc[i][j][q] = 0.f;

    const int ar = lane >> 2, ac = lane & 3;

    for (int ch = 0; ch < NCH; ch++) {
        CP_WAIT1();
        __syncthreads();
        const uint32_t* as = (const uint32_t*)(sm + (ch & 1) * AS_BUF);
        const uint32_t* bs = (const uint32_t*)(sm + 2 * AS_BUF + (ch & 1) * BS_BUF);

#pragma unroll
        for (int ks = 0; ks < 4; ks++) {
            uint32_t afr[4][4], bfr[4][2];
#pragma unroll
            for (int mf = 0; mf < 4; mf++) {
                int r = wm + mf * 16 + ar;
                int c = ks * 8 + ac;
                afr[mf][0] = as[r * AS_STRIDE + c];
                afr[mf][1] = as[(r + 8) * AS_STRIDE + c];
                afr[mf][2] = as[r * AS_STRIDE + c + 4];
                afr[mf][3] = as[(r + 8) * AS_STRIDE + c + 4];
            }
#pragma unroll
            for (int nf = 0; nf < 4; nf++) {
                int c = wn + nf * 8 + ar;
                bfr[nf][0] = bs[(ks * 8 + ac) * BS_STRIDE + c];
                bfr[nf][1] = bs[(ks * 8 + 4 + ac) * BS_STRIDE + c];
            }
#pragma unroll
            for (int mf = 0; mf < 4; mf++)
#pragma unroll
                for (int nf = 0; nf < 4; nf++)
                    MMA_TF32(acc[mf][nf], afr[mf], bfr[nf]);
        }
        __syncthreads();

        if (ch + 2 < NCH) {
            int k0 = (ch + 2) * 32;
            int st = ch & 1;
#pragma unroll
            for (int i = 0; i < 4; i++) {
                int m = am + i * 32;
                cpasync16(asb[st] + (uint32_t)(m * AS_STRIDE + aq * 4) * 4,
                          Ag + (size_t)m * GK + k0 + aq * 4);
            }
#pragma unroll
            for (int i = 0; i < 4; i++) {
                int k = bk + i * 8;
                cpasync16(bsb[st] + (uint32_t)(k * BS_STRIDE + bq * 4) * 4,
                          Bg + (size_t)(k0 + k) * GN + p0 + bq * 4);
            }
        }
        CP_COMMIT();
    }

    float* Cb = Cc + (size_t)b * GM * GN;
    const int obase = m0 + wm;
    const int pbase = p0 + wn;
#pragma unroll
    for (int mf = 0; mf < 4; mf++) {
#pragma unroll
        for (int nf = 0; nf < 4; nf++) {
            int o = obase + mf * 16 + ar;
            int p = pbase + nf * 8 + 2 * ac;
            float2 v0, v1;
            v0.x = fmaxf(acc[mf][nf][0], 0.f);
            v0.y = fmaxf(acc[mf][nf][1], 0.f);
            v1.x = fmaxf(acc[mf][nf][2], 0.f);
            v1.y = fmaxf(acc[mf][nf][3], 0.f);
            *(float2*)(Cb + (size_t)o * GN + p) = v0;
            *(float2*)(Cb + (size_t)(o + 8) * GN + p) = v1;
        }
    }
}

// ---------------- host side ----------------------------------------------------
static void run_layer(const float* xin, const float* w_off, const float* b_off,
                      const float* wmain, float* outp,
                      float* col, float* om, float* om_part, float* wtf) {
    dim3 gOff(36, 8, B);
    offset_conv_kernel<<<gOff, 256>>>(xin, w_off, om_part);
    reduce_om_kernel<<<(B * 27 * HW) / 256, 256>>>(om_part, b_off, om);
    wcvt_kernel<<<(GM * GK) / 256, 256>>>(wmain, wtf);
    dim3 gSamp(36, KK * 4, B);
    sample_kernel<<<gSamp, 256>>>(xin, om, col);
    dim3 gGemm(GN / 128, GM / 128, B);
    gemm_tf32_kernel<<<gGemm, 256, SM_FLOATS * 4>>>(wtf, col, outp);
}

extern "C" void kernel_launch(void* const* d_in, const int* in_sizes, int n_in,
                              void* d_out, int out_size) {
    const float* x      = (const float*)d_in[0];
    const float* w_off0 = (const float*)d_in[1];
    const float* b_off0 = (const float*)d_in[2];
    const float* w0     = (const float*)d_in[3];
    const float* w_off1 = (const float*)d_in[4];
    const float* b_off1 = (const float*)d_in[5];
    const float* w1     = (const float*)d_in[6];
    float* out = (float*)d_out;

    static bool attr_set = false;
    if (!attr_set) {
        cudaFuncSetAttribute(gemm_tf32_kernel,
                             cudaFuncAttributeMaxDynamicSharedMemorySize, SM_FLOATS * 4);
        attr_set = true;
    }

    float *col, *om, *om_part, *hbuf, *wtf;
    cudaGetSymbolAddress((void**)&col,     g_col);
    cudaGetSymbolAddress((void**)&om,      g_om);
    cudaGetSymbolAddress((void**)&om_part, g_om_part);
    cudaGetSymbolAddress((void**)&hbuf,    g_h);
    cudaGetSymbolAddress((void**)&wtf,     g_wtf);

    run_layer(x,    w_off0, b_off0, w0, hbuf, col, om, om_part, wtf);
    run_layer(hbuf, w_off1, b_off1, w1, out,  col, om, om_part, wtf);
}